// round 16
// baseline (speedup 1.0000x reference)
#include <cuda_runtime.h>
#include <math.h>

// ---------------- problem constants ----------------
#define B_  4
#define C_  192
#define T_  2048
#define H_  2
#define KC_ 96
#define FC_ 768
#define L_  6
#define SCALE_ 0.10206207261596577f   // 96^-0.5
#define EPS_ 1e-5f

// ---------------- tf32 mma.sync helpers ----------------
__device__ __forceinline__ float to_tf32(float x) {
    unsigned r; asm("cvt.rna.tf32.f32 %0, %1;" : "=r"(r) : "f"(x));
    return __uint_as_float(r);
}
__device__ __forceinline__ void mma_tf32(float* d, const float* a, const float* b) {
    asm("mma.sync.aligned.m16n8k8.row.col.f32.tf32.tf32.f32 "
        "{%0,%1,%2,%3}, {%4,%5,%6,%7}, {%8,%9}, {%0,%1,%2,%3};"
        : "+f"(d[0]), "+f"(d[1]), "+f"(d[2]), "+f"(d[3])
        : "r"(__float_as_uint(a[0])), "r"(__float_as_uint(a[1])),
          "r"(__float_as_uint(a[2])), "r"(__float_as_uint(a[3])),
          "r"(__float_as_uint(b[0])), "r"(__float_as_uint(b[1])));
}

// ---------------- scratch (no allocations allowed) ----------------
__device__ float g_x[B_*C_*T_];
__device__ float g_q[B_*C_*T_];
__device__ float g_k[B_*C_*T_];
__device__ float g_v[B_*C_*T_];
__device__ float g_a[B_*C_*T_];
__device__ float g_t[B_*C_*T_];
__device__ float g_f[B_*FC_*T_];

// ---------------- elementwise mask multiply ----------------
__global__ void k_maskmul(const float* __restrict__ in, const float* __restrict__ msk,
                          float* __restrict__ out)
{
    int idx = blockIdx.x * blockDim.x + threadIdx.x;
    if (idx >= B_*C_*T_) return;
    int b = idx / (C_*T_);
    int t = idx % T_;
    out[idx] = in[idx] * msk[b*T_ + t];
}

// ---------------- tensor-core GEMM/conv body (tf32 mma.sync) ----------------
// Register-prefetch double buffering (validated R12).
template<int KW>
__device__ __forceinline__ void mma_body(
    const float* __restrict__ Xb, const float* __restrict__ Wg,
    const float* __restrict__ bias, float* __restrict__ Yb,
    int Cin, int relu, int m0, int t0, int c_begin, int c_end)
{
    constexpr int BM = 64, BN = 64, BK = 32;
    constexpr int PADW = (KW - 1) / 2;
    constexpr int XV = BN + KW - 1;
    constexpr int ST = 72;               // 72 mod 32 == 8 -> conflict-free frags
    constexpr int NW = BM*BK*KW/256;     // W elems per thread (8 or 24)
    constexpr int NX = (BK*XV + 255)/256;// X elems per thread (8 or 9)

    __shared__ float Ws[KW][BK][ST];
    __shared__ float Xs[BK][ST];

    const int tid  = threadIdx.x;
    const int lane = tid & 31, wid = tid >> 5;
    const int wm = wid >> 2, wn = wid & 3;
    const int g = lane >> 2, tig = lane & 3;
    const int mb = wm * 32, nb = wn * 16;

    float acc[2][2][4] = {};
    float wr[NW], xr[NX];

    {
        int c0 = c_begin;
        #pragma unroll
        for (int j = 0; j < NW; j++) {
            int idx = tid + j*256;
            int o  = idx / (BK*KW);
            int ck = idx - o * (BK*KW);
            int c  = ck / KW, k = ck - c * KW;
            wr[j] = Wg[((size_t)(m0 + o) * Cin + c0 + c) * KW + k];
        }
        #pragma unroll
        for (int j = 0; j < NX; j++) {
            int idx = tid + j*256;
            if (idx < BK*XV) {
                int c = idx / XV, u = idx - c * XV;
                int t = t0 - PADW + u;
                xr[j] = (t >= 0 && t < T_) ? Xb[(size_t)(c0 + c) * T_ + t] : 0.f;
            }
        }
    }

    for (int c0 = c_begin; c0 < c_end; c0 += BK) {
        __syncthreads();

        #pragma unroll
        for (int j = 0; j < NW; j++) {
            int idx = tid + j*256;
            int o  = idx / (BK*KW);
            int ck = idx - o * (BK*KW);
            int c  = ck / KW, k = ck - c * KW;
            Ws[k][c][o] = to_tf32(wr[j]);
        }
        #pragma unroll
        for (int j = 0; j < NX; j++) {
            int idx = tid + j*256;
            if (idx < BK*XV) {
                int c = idx / XV, u = idx - c * XV;
                Xs[c][u] = to_tf32(xr[j]);
            }
        }
        __syncthreads();

        if (c0 + BK < c_end) {
            int cn = c0 + BK;
            #pragma unroll
            for (int j = 0; j < NW; j++) {
                int idx = tid + j*256;
                int o  = idx / (BK*KW);
                int ck = idx - o * (BK*KW);
                int c  = ck / KW, k = ck - c * KW;
                wr[j] = Wg[((size_t)(m0 + o) * Cin + cn + c) * KW + k];
            }
            #pragma unroll
            for (int j = 0; j < NX; j++) {
                int idx = tid + j*256;
                if (idx < BK*XV) {
                    int c = idx / XV, u = idx - c * XV;
                    int t = t0 - PADW + u;
                    xr[j] = (t >= 0 && t < T_) ? Xb[(size_t)(cn + c) * T_ + t] : 0.f;
                }
            }
        }

        #pragma unroll
        for (int kk = 0; kk < BK; kk += 8) {
            #pragma unroll
            for (int kw = 0; kw < KW; kw++) {
                float a[2][4], b[2][2];
                #pragma unroll
                for (int i = 0; i < 2; i++) {
                    a[i][0] = Ws[kw][kk + tig    ][mb + i*16 + g    ];
                    a[i][1] = Ws[kw][kk + tig    ][mb + i*16 + g + 8];
                    a[i][2] = Ws[kw][kk + tig + 4][mb + i*16 + g    ];
                    a[i][3] = Ws[kw][kk + tig + 4][mb + i*16 + g + 8];
                }
                #pragma unroll
                for (int j = 0; j < 2; j++) {
                    b[j][0] = Xs[kk + tig    ][nb + j*8 + g + kw];
                    b[j][1] = Xs[kk + tig + 4][nb + j*8 + g + kw];
                }
                #pragma unroll
                for (int i = 0; i < 2; i++)
                    #pragma unroll
                    for (int j = 0; j < 2; j++)
                        mma_tf32(acc[i][j], a[i], b[j]);
            }
        }
    }

    #pragma unroll
    for (int i = 0; i < 2; i++) {
        int o0 = m0 + mb + i*16 + g;
        float b0 = bias ? bias[o0]     : 0.f;
        float b8 = bias ? bias[o0 + 8] : 0.f;
        #pragma unroll
        for (int j = 0; j < 2; j++) {
            int t = t0 + nb + j*8 + 2*tig;
            float2 v0 = make_float2(acc[i][j][0] + b0, acc[i][j][1] + b0);
            float2 v1 = make_float2(acc[i][j][2] + b8, acc[i][j][3] + b8);
            if (relu) {
                v0.x = fmaxf(v0.x, 0.f); v0.y = fmaxf(v0.y, 0.f);
                v1.x = fmaxf(v1.x, 0.f); v1.y = fmaxf(v1.y, 0.f);
            }
            *reinterpret_cast<float2*>(&Yb[(size_t)o0       * T_ + t]) = v0;
            *reinterpret_cast<float2*>(&Yb[(size_t)(o0 + 8) * T_ + t]) = v1;
        }
    }
}

template<int KW>
__global__ __launch_bounds__(256) void k_mma(
    const float* __restrict__ X, const float* __restrict__ Wg,
    const float* __restrict__ bias, float* __restrict__ Y,
    int M, int Cin, int relu)
{
    const int b = blockIdx.z;
    mma_body<KW>(X + (size_t)b * Cin * T_, Wg, bias, Y + (size_t)b * M * T_,
                 Cin, relu, blockIdx.y * 64, blockIdx.x * 64, 0, Cin);
}

__global__ __launch_bounds__(256) void k_qkv(
    const float* __restrict__ X,
    const float* __restrict__ Wq, const float* __restrict__ bq, float* __restrict__ Yq,
    const float* __restrict__ Wk, const float* __restrict__ bk, float* __restrict__ Yk,
    const float* __restrict__ Wv, const float* __restrict__ bv, float* __restrict__ Yv)
{
    const int b = blockIdx.z;
    const int mat = blockIdx.y / 3;
    const int m0  = (blockIdx.y % 3) * 64;
    const float *W, *bi; float *Y;
    if (mat == 0)      { W = Wq; bi = bq; Y = Yq; }
    else if (mat == 1) { W = Wk; bi = bk; Y = Yk; }
    else               { W = Wv; bi = bv; Y = Yv; }
    mma_body<1>(X + (size_t)b * C_ * T_, W, bi, Y + (size_t)b * C_ * T_,
                C_, 0, m0, blockIdx.x * 64, 0, C_);
}

__global__ __launch_bounds__(256) void k_conv2split(
    const float* __restrict__ X, const float* __restrict__ Wg,
    const float* __restrict__ bias, float* __restrict__ Y1, float* __restrict__ Y2)
{
    const int b = blockIdx.z;
    const int half = blockIdx.y / 3;
    const int m0   = (blockIdx.y % 3) * 64;
    float* Y = half ? Y2 : Y1;
    mma_body<3>(X + (size_t)b * FC_ * T_, Wg, half ? nullptr : bias,
                Y + (size_t)b * C_ * T_, FC_, 0, m0, blockIdx.x * 64,
                half * (FC_/2), (half + 1) * (FC_/2));
}

// ---------------- flash attention with fused rel-K band + rel-V correction ----
// R13: Vs stored [d][s] (same as Ks) -> K/V loads are float4-vectorized and
// bank-conflict-free; PV B-fragments reindexed (still conflict-free).
// tf32 RNA cvt still applied per element in registers -> math identical.
__global__ __launch_bounds__(128) void k_flash(
    const float* __restrict__ Q, const float* __restrict__ Kp, const float* __restrict__ V,
    const float* __restrict__ erk, const float* __restrict__ erv,
    float* __restrict__ O)
{
    constexpr int BR = 64, BC = 64, D = 96;
    constexpr int QSTR = 100, KSTR = 68, VSTR = 68, PSTR = 68;
    extern __shared__ float sm[];
    float* Qs = sm;                  // BR*QSTR  [r][d] tf32(q*scale)
    float* Ks = Qs + BR*QSTR;        // D*KSTR   [d][s] tf32
    float* Vs = Ks + D*KSTR;         // D*VSTR   [d][s] tf32
    float* Ps = Vs + D*VSTR;         // BR*PSTR  [r][s] tf32 probabilities
    float* qr = Ps + BR*PSTR;        // BR*9     q . erk
    float* bs = qr + BR*9;           // BR*12    band scores (init -1e30)
    float* ev = bs + BR*12;          // 9*96     erv staged

    const int t0 = blockIdx.x * BR;
    const int h = blockIdx.y, b = blockIdx.z;
    const size_t base = ((size_t)b * C_ + h * KC_) * T_;
    const float* Qb = Q + base;
    const float* Kb = Kp + base;
    const float* Vb = V + base;

    const int tid  = threadIdx.x;
    const int lane = tid & 31, w = tid >> 5;
    const int g = lane >> 2, tig = lane & 3;
    const int w16 = w * 16;

    for (int idx = tid; idx < D*BR; idx += 128) {
        int d = idx / BR, r = idx - d * BR;
        Qs[r*QSTR + d] = to_tf32(Qb[(size_t)d * T_ + t0 + r] * SCALE_);
    }
    for (int idx = tid; idx < 9*96; idx += 128) ev[idx] = erv[idx];
    for (int idx = tid; idx < BR*12; idx += 128) bs[idx] = -1e30f;
    __syncthreads();
    for (int idx = tid; idx < BR * 9; idx += 128) {
        int r = idx / 9, dd = idx - r * 9;
        float s = 0.f;
        #pragma unroll 8
        for (int d = 0; d < D; d++) s = fmaf(Qs[r*QSTR + d], erk[dd*KC_ + d], s);
        qr[idx] = s;
    }

    float m_i[2] = {-1e30f, -1e30f};
    float l_i[2] = {0.f, 0.f};
    float oa[12][4] = {};

    for (int s0 = 0; s0 < T_; s0 += BC) {
        __syncthreads();
        // vectorized K/V tile load: 96 rows x 16 float4 chunks each
        #pragma unroll
        for (int j = 0; j < 12; j++) {
            int idx = tid + j*128;           // 0 .. 1535
            int d  = idx >> 4;
            int s4 = (idx & 15) * 4;
            float4 kv = *reinterpret_cast<const float4*>(&Kb[(size_t)d * T_ + s0 + s4]);
            float4 vv = *reinterpret_cast<const float4*>(&Vb[(size_t)d * T_ + s0 + s4]);
            float4 kо = make_float4(to_tf32(kv.x), to_tf32(kv.y), to_tf32(kv.z), to_tf32(kv.w));
            float4 vo = make_float4(to_tf32(vv.x), to_tf32(vv.y), to_tf32(vv.z), to_tf32(vv.w));
            *reinterpret_cast<float4*>(&Ks[d*KSTR + s4]) = kо;
            *reinterpret_cast<float4*>(&Vs[d*VSTR + s4]) = vo;
        }
        __syncthreads();

        // ---- S = Q K^T ----
        float acc[8][4];
        #pragma unroll
        for (int nf = 0; nf < 8; nf++)
            #pragma unroll
            for (int e = 0; e < 4; e++) acc[nf][e] = 0.f;

        #pragma unroll
        for (int kk = 0; kk < D; kk += 8) {
            float a[4];
            a[0] = Qs[(w16 + g    )*QSTR + kk + tig    ];
            a[1] = Qs[(w16 + g + 8)*QSTR + kk + tig    ];
            a[2] = Qs[(w16 + g    )*QSTR + kk + tig + 4];
            a[3] = Qs[(w16 + g + 8)*QSTR + kk + tig + 4];
            #pragma unroll
            for (int nf = 0; nf < 8; nf++) {
                float bfr[2];
                bfr[0] = Ks[(kk + tig    )*KSTR + nf*8 + g];
                bfr[1] = Ks[(kk + tig + 4)*KSTR + nf*8 + g];
                mma_tf32(acc[nf], a, bfr);
            }
        }

        // ---- rel-K band add + band-score spill (diagonal tiles only) ----
        if (s0 + BC + 4 > t0 && s0 < t0 + BR + 5) {
            #pragma unroll
            for (int nf = 0; nf < 8; nf++)
                #pragma unroll
                for (int e = 0; e < 2; e++) {
                    int col = s0 + nf*8 + 2*tig + e;
                    int r0 = t0 + w16 + g;
                    int d0 = col - r0;
                    if (d0 >= -4 && d0 <= 4) {
                        acc[nf][e] += qr[(w16 + g)*9 + d0 + 4];
                        bs[(w16 + g)*12 + d0 + 4] = acc[nf][e];
                    }
                    int d1 = col - (r0 + 8);
                    if (d1 >= -4 && d1 <= 4) {
                        acc[nf][e + 2] += qr[(w16 + g + 8)*9 + d1 + 4];
                        bs[(w16 + g + 8)*12 + d1 + 4] = acc[nf][e + 2];
                    }
                }
        }

        // ---- online softmax (rows g and g+8; reduce over tig group) ----
        #pragma unroll
        for (int i = 0; i < 2; i++) {
            float mx = -1e30f;
            #pragma unroll
            for (int nf = 0; nf < 8; nf++)
                mx = fmaxf(mx, fmaxf(acc[nf][2*i], acc[nf][2*i + 1]));
            mx = fmaxf(mx, __shfl_xor_sync(0xffffffffu, mx, 1));
            mx = fmaxf(mx, __shfl_xor_sync(0xffffffffu, mx, 2));
            float mn = fmaxf(m_i[i], mx);
            float al = __expf(m_i[i] - mn);
            float rs = 0.f;
            int row = w16 + g + 8*i;
            #pragma unroll
            for (int nf = 0; nf < 8; nf++) {
                float p0 = to_tf32(__expf(acc[nf][2*i    ] - mn));
                float p1 = to_tf32(__expf(acc[nf][2*i + 1] - mn));
                *reinterpret_cast<float2*>(&Ps[row*PSTR + nf*8 + 2*tig]) = make_float2(p0, p1);
                rs += p0 + p1;
            }
            rs += __shfl_xor_sync(0xffffffffu, rs, 1);
            rs += __shfl_xor_sync(0xffffffffu, rs, 2);
            l_i[i] = l_i[i] * al + rs;
            m_i[i] = mn;
            #pragma unroll
            for (int nf = 0; nf < 12; nf++) {
                oa[nf][2*i] *= al; oa[nf][2*i + 1] *= al;
            }
        }
        __syncwarp();

        // ---- O += P @ V : B-fragment from Vs [d][s] (n=d, k=s) ----
        #pragma unroll
        for (int kk = 0; kk < BC; kk += 8) {
            float pa[4];
            pa[0] = Ps[(w16 + g    )*PSTR + kk + tig    ];
            pa[1] = Ps[(w16 + g + 8)*PSTR + kk + tig    ];
            pa[2] = Ps[(w16 + g    )*PSTR + kk + tig + 4];
            pa[3] = Ps[(w16 + g + 8)*PSTR + kk + tig + 4];
            #pragma unroll
            for (int nf = 0; nf < 12; nf++) {
                float bfr[2];
                bfr[0] = Vs[(nf*8 + g)*VSTR + kk + tig    ];
                bfr[1] = Vs[(nf*8 + g)*VSTR + kk + tig + 4];
                mma_tf32(oa[nf], pa, bfr);
            }
        }
    }
    __syncthreads();   // also orders bs writes before epilogue reads

    // ---- epilogue: band probs from final (m,l); normalize + add erv term ----
    {
        float inv0 = 1.f / l_i[0], inv1 = 1.f / l_i[1];
        float p0[9], p1[9];
        #pragma unroll
        for (int dd = 0; dd < 9; dd++) {
            p0[dd] = __expf(bs[(w16 + g    )*12 + dd] - m_i[0]) * inv0;
            p1[dd] = __expf(bs[(w16 + g + 8)*12 + dd] - m_i[1]) * inv1;
        }
        #pragma unroll
        for (int nf = 0; nf < 12; nf++) {
            #pragma unroll
            for (int e = 0; e < 2; e++) {
                int d = nf*8 + 2*tig + e;
                float add0 = 0.f, add1 = 0.f;
                #pragma unroll
                for (int dd = 0; dd < 9; dd++) {
                    float evd = ev[dd*96 + d];
                    add0 = fmaf(p0[dd], evd, add0);
                    add1 = fmaf(p1[dd], evd, add1);
                }
                Qs[d*BR + w16 + g    ] = oa[nf][e    ] * inv0 + add0;
                Qs[d*BR + w16 + g + 8] = oa[nf][e + 2] * inv1 + add1;
            }
        }
    }
    __syncthreads();
    float* Ob = O + base;
    for (int idx = tid; idx < D*BR; idx += 128) {
        int d = idx / BR, r = idx - d * BR;
        Ob[(size_t)d * T_ + t0 + r] = Qs[idx];
    }
}

// ---------------- fused residual-add + channel LayerNorm ----------------
__global__ __launch_bounds__(256) void k_addln(
    float* __restrict__ X, const float* __restrict__ R,
    const float* __restrict__ gg, const float* __restrict__ be)
{
    const int tx = threadIdx.x, ty = threadIdx.y;
    const int t = blockIdx.x * 32 + tx;
    const int b = blockIdx.y;

    float vals[24];
    float s = 0.f, sq = 0.f;
    #pragma unroll
    for (int k = 0; k < 24; k++) {
        int c = ty + k * 8;
        size_t idx = ((size_t)b * C_ + c) * T_ + t;
        float v = X[idx] + R[idx];
        vals[k] = v; s += v; sq += v * v;
    }
    __shared__ float ss[8][33], sg[8][33];
    ss[ty][tx] = s; sg[ty][tx] = sq;
    __syncthreads();
    if (ty == 0) {
        float a = 0.f, q = 0.f;
        #pragma unroll
        for (int k = 0; k < 8; k++) { a += ss[k][tx]; q += sg[k][tx]; }
        ss[0][tx] = a; sg[0][tx] = q;
    }
    __syncthreads();
    const float mean = ss[0][tx] * (1.f / C_);
    const float var  = sg[0][tx] * (1.f / C_) - mean * mean;
    const float rstd = rsqrtf(var + EPS_);
    #pragma unroll
    for (int k = 0; k < 24; k++) {
        int c = ty + k * 8;
        size_t idx = ((size_t)b * C_ + c) * T_ + t;
        X[idx] = (vals[k] - mean) * rstd * gg[c] + be[c];
    }
}

__global__ __launch_bounds__(256) void k_addln3(
    float* __restrict__ X, const float* __restrict__ R1, const float* __restrict__ R2,
    const float* __restrict__ gg, const float* __restrict__ be)
{
    const int tx = threadIdx.x, ty = threadIdx.y;
    const int t = blockIdx.x * 32 + tx;
    const int b = blockIdx.y;

    float vals[24];
    float s = 0.f, sq = 0.f;
    #pragma unroll
    for (int k = 0; k < 24; k++) {
        int c = ty + k * 8;
        size_t idx = ((size_t)b * C_ + c) * T_ + t;
        float v = X[idx] + R1[idx] + R2[idx];
        vals[k] = v; s += v; sq += v * v;
    }
    __shared__ float ss[8][33], sg[8][33];
    ss[ty][tx] = s; sg[ty][tx] = sq;
    __syncthreads();
    if (ty == 0) {
        float a = 0.f, q = 0.f;
        #pragma unroll
        for (int k = 0; k < 8; k++) { a += ss[k][tx]; q += sg[k][tx]; }
        ss[0][tx] = a; sg[0][tx] = q;
    }
    __syncthreads();
    const float mean = ss[0][tx] * (1.f / C_);
    const float var  = sg[0][tx] * (1.f / C_) - mean * mean;
    const float rstd = rsqrtf(var + EPS_);
    #pragma unroll
    for (int k = 0; k < 24; k++) {
        int c = ty + k * 8;
        size_t idx = ((size_t)b * C_ + c) * T_ + t;
        X[idx] = (vals[k] - mean) * rstd * gg[c] + be[c];
    }
}

// ---------------- launcher ----------------
extern "C" void kernel_launch(void* const* d_in, const int* in_sizes, int n_in,
                              void* d_out, int out_size)
{
    (void)in_sizes; (void)n_in; (void)out_size;
    const float* x   = (const float*)d_in[0];
    const float* msk = (const float*)d_in[1];
    const float* Wq  = (const float*)d_in[2];
    const float* bq  = (const float*)d_in[3];
    const float* Wk  = (const float*)d_in[4];
    const float* bk  = (const float*)d_in[5];
    const float* Wv  = (const float*)d_in[6];
    const float* bv  = (const float*)d_in[7];
    const float* Wo  = (const float*)d_in[8];
    const float* bo  = (const float*)d_in[9];
    const float* erk = (const float*)d_in[10];
    const float* erv = (const float*)d_in[11];
    const float* g1  = (const float*)d_in[12];
    const float* be1 = (const float*)d_in[13];
    const float* fw1 = (const float*)d_in[14];
    const float* fb1 = (const float*)d_in[15];
    const float* fw2 = (const float*)d_in[16];
    const float* fb2 = (const float*)d_in[17];
    const float* g2  = (const float*)d_in[18];
    const float* be2 = (const float*)d_in[19];

    float *xb, *qb, *kb, *vb, *ab, *tb, *fb;
    cudaGetSymbolAddress((void**)&xb, g_x);
    cudaGetSymbolAddress((void**)&qb, g_q);
    cudaGetSymbolAddress((void**)&kb, g_k);
    cudaGetSymbolAddress((void**)&vb, g_v);
    cudaGetSymbolAddress((void**)&ab, g_a);
    cudaGetSymbolAddress((void**)&tb, g_t);
    cudaGetSymbolAddress((void**)&fb, g_f);

    constexpr int FLASH_SMEM =
        (64*100 + 96*68 + 96*68 + 64*68 + 64*9 + 64*12 + 9*96) * 4;
    cudaFuncSetAttribute(k_flash, cudaFuncAttributeMaxDynamicSharedMemorySize, FLASH_SMEM);

    k_maskmul<<<(B_*C_*T_ + 255)/256, 256>>>(x, msk, xb);

    for (int i = 0; i < L_; i++) {
        k_qkv<<<dim3(T_/64, 9, B_), 256>>>(
            xb,
            Wq + (size_t)i*C_*C_, bq + i*C_, qb,
            Wk + (size_t)i*C_*C_, bk + i*C_, kb,
            Wv + (size_t)i*C_*C_, bv + i*C_, vb);

        k_flash<<<dim3(T_/64, H_, B_), 128, FLASH_SMEM>>>(
            qb, kb, vb, erk + (size_t)i*9*KC_, erv + (size_t)i*9*KC_, ab);

        k_mma<1><<<dim3(T_/64, C_/64, B_), 256>>>(
            ab, Wo + (size_t)i*C_*C_, bo + i*C_, tb, C_, C_, 0);
        k_addln<<<dim3(T_/32, B_), dim3(32, 8)>>>(xb, tb, g1 + i*C_, be1 + i*C_);

        k_mma<3><<<dim3(T_/64, FC_/64, B_), 256>>>(
            xb, fw1 + (size_t)i*FC_*C_*3, fb1 + i*FC_, fb, FC_, C_, 1);

        k_conv2split<<<dim3(T_/64, 6, B_), 256>>>(
            fb, fw2 + (size_t)i*C_*FC_*3, fb2 + i*C_, tb, ab);
        k_addln3<<<dim3(T_/32, B_), dim3(32, 8)>>>(xb, tb, ab, g2 + i*C_, be2 + i*C_);
    }

    k_maskmul<<<(B_*C_*T_ + 255)/256, 256>>>(xb, msk, (float*)d_out);
}

// round 17
// speedup vs baseline: 1.5836x; 1.5836x over previous
#include <cuda_runtime.h>
#include <math.h>

// ---------------- problem constants ----------------
#define B_  4
#define C_  192
#define T_  2048
#define H_  2
#define KC_ 96
#define FC_ 768
#define L_  6
#define SCALE_ 0.10206207261596577f   // 96^-0.5
#define EPS_ 1e-5f

// ---------------- tf32 mma.sync helpers ----------------
__device__ __forceinline__ float to_tf32(float x) {
    unsigned r; asm("cvt.rna.tf32.f32 %0, %1;" : "=r"(r) : "f"(x));
    return __uint_as_float(r);
}
__device__ __forceinline__ void mma_tf32(float* d, const float* a, const float* b) {
    asm("mma.sync.aligned.m16n8k8.row.col.f32.tf32.tf32.f32 "
        "{%0,%1,%2,%3}, {%4,%5,%6,%7}, {%8,%9}, {%0,%1,%2,%3};"
        : "+f"(d[0]), "+f"(d[1]), "+f"(d[2]), "+f"(d[3])
        : "r"(__float_as_uint(a[0])), "r"(__float_as_uint(a[1])),
          "r"(__float_as_uint(a[2])), "r"(__float_as_uint(a[3])),
          "r"(__float_as_uint(b[0])), "r"(__float_as_uint(b[1])));
}

// ---------------- scratch (no allocations allowed) ----------------
__device__ float g_x[B_*C_*T_];
__device__ float g_q[B_*C_*T_];
__device__ float g_k[B_*C_*T_];
__device__ float g_v[B_*C_*T_];
__device__ float g_a[B_*C_*T_];
__device__ float g_t[B_*C_*T_];
__device__ float g_f[B_*FC_*T_];

// ---------------- elementwise mask multiply ----------------
__global__ void k_maskmul(const float* __restrict__ in, const float* __restrict__ msk,
                          float* __restrict__ out)
{
    int idx = blockIdx.x * blockDim.x + threadIdx.x;
    if (idx >= B_*C_*T_) return;
    int b = idx / (C_*T_);
    int t = idx % T_;
    out[idx] = in[idx] * msk[b*T_ + t];
}

// ---------------- tensor-core GEMM/conv body (tf32 mma.sync) ----------------
// Register-prefetch (R12) + double-buffered smem with ONE barrier per tile (R17).
// Safety: a warp reaches sync_i only after finishing compute_{i-1}; hence after
// sync_i the non-current buffer has no readers and may be overwritten.
template<int KW>
__device__ __forceinline__ void mma_body(
    const float* __restrict__ Xb, const float* __restrict__ Wg,
    const float* __restrict__ bias, float* __restrict__ Yb,
    int Cin, int relu, int m0, int t0, int c_begin, int c_end)
{
    constexpr int BM = 64, BN = 64, BK = 32;
    constexpr int PADW = (KW - 1) / 2;
    constexpr int XV = BN + KW - 1;
    constexpr int ST = 72;               // 72 mod 32 == 8 -> conflict-free frags
    constexpr int NW = BM*BK*KW/256;     // W elems per thread (8 or 24)
    constexpr int NX = (BK*XV + 255)/256;// X elems per thread (8 or 9)

    __shared__ float Ws[2][KW][BK][ST];
    __shared__ float Xs[2][BK][ST];

    const int tid  = threadIdx.x;
    const int lane = tid & 31, wid = tid >> 5;
    const int wm = wid >> 2, wn = wid & 3;
    const int g = lane >> 2, tig = lane & 3;
    const int mb = wm * 32, nb = wn * 16;

    float acc[2][2][4] = {};
    float wr[NW], xr[NX];

    // ---- prologue: load first tile into registers ----
    {
        int c0 = c_begin;
        #pragma unroll
        for (int j = 0; j < NW; j++) {
            int idx = tid + j*256;
            int o  = idx / (BK*KW);
            int ck = idx - o * (BK*KW);
            int c  = ck / KW, k = ck - c * KW;
            wr[j] = Wg[((size_t)(m0 + o) * Cin + c0 + c) * KW + k];
        }
        #pragma unroll
        for (int j = 0; j < NX; j++) {
            int idx = tid + j*256;
            if (idx < BK*XV) {
                int c = idx / XV, u = idx - c * XV;
                int t = t0 - PADW + u;
                xr[j] = (t >= 0 && t < T_) ? Xb[(size_t)(c0 + c) * T_ + t] : 0.f;
            }
        }
    }

    int p = 0;
    for (int c0 = c_begin; c0 < c_end; c0 += BK, p ^= 1) {
        // ---- store prefetched tile to smem buffer p (tf32 RNA at STS) ----
        #pragma unroll
        for (int j = 0; j < NW; j++) {
            int idx = tid + j*256;
            int o  = idx / (BK*KW);
            int ck = idx - o * (BK*KW);
            int c  = ck / KW, k = ck - c * KW;
            Ws[p][k][c][o] = to_tf32(wr[j]);
        }
        #pragma unroll
        for (int j = 0; j < NX; j++) {
            int idx = tid + j*256;
            if (idx < BK*XV) {
                int c = idx / XV, u = idx - c * XV;
                Xs[p][c][u] = to_tf32(xr[j]);
            }
        }
        __syncthreads();                 // the ONLY barrier per tile

        // ---- issue next tile's gmem loads (overlap with compute below) ----
        if (c0 + BK < c_end) {
            int cn = c0 + BK;
            #pragma unroll
            for (int j = 0; j < NW; j++) {
                int idx = tid + j*256;
                int o  = idx / (BK*KW);
                int ck = idx - o * (BK*KW);
                int c  = ck / KW, k = ck - c * KW;
                wr[j] = Wg[((size_t)(m0 + o) * Cin + cn + c) * KW + k];
            }
            #pragma unroll
            for (int j = 0; j < NX; j++) {
                int idx = tid + j*256;
                if (idx < BK*XV) {
                    int c = idx / XV, u = idx - c * XV;
                    int t = t0 - PADW + u;
                    xr[j] = (t >= 0 && t < T_) ? Xb[(size_t)(cn + c) * T_ + t] : 0.f;
                }
            }
        }

        // ---- compute from buffer p ----
        #pragma unroll
        for (int kk = 0; kk < BK; kk += 8) {
            #pragma unroll
            for (int kw = 0; kw < KW; kw++) {
                float a[2][4], b[2][2];
                #pragma unroll
                for (int i = 0; i < 2; i++) {
                    a[i][0] = Ws[p][kw][kk + tig    ][mb + i*16 + g    ];
                    a[i][1] = Ws[p][kw][kk + tig    ][mb + i*16 + g + 8];
                    a[i][2] = Ws[p][kw][kk + tig + 4][mb + i*16 + g    ];
                    a[i][3] = Ws[p][kw][kk + tig + 4][mb + i*16 + g + 8];
                }
                #pragma unroll
                for (int j = 0; j < 2; j++) {
                    b[j][0] = Xs[p][kk + tig    ][nb + j*8 + g + kw];
                    b[j][1] = Xs[p][kk + tig + 4][nb + j*8 + g + kw];
                }
                #pragma unroll
                for (int i = 0; i < 2; i++)
                    #pragma unroll
                    for (int j = 0; j < 2; j++)
                        mma_tf32(acc[i][j], a[i], b[j]);
            }
        }
    }

    #pragma unroll
    for (int i = 0; i < 2; i++) {
        int o0 = m0 + mb + i*16 + g;
        float b0 = bias ? bias[o0]     : 0.f;
        float b8 = bias ? bias[o0 + 8] : 0.f;
        #pragma unroll
        for (int j = 0; j < 2; j++) {
            int t = t0 + nb + j*8 + 2*tig;
            float2 v0 = make_float2(acc[i][j][0] + b0, acc[i][j][1] + b0);
            float2 v1 = make_float2(acc[i][j][2] + b8, acc[i][j][3] + b8);
            if (relu) {
                v0.x = fmaxf(v0.x, 0.f); v0.y = fmaxf(v0.y, 0.f);
                v1.x = fmaxf(v1.x, 0.f); v1.y = fmaxf(v1.y, 0.f);
            }
            *reinterpret_cast<float2*>(&Yb[(size_t)o0       * T_ + t]) = v0;
            *reinterpret_cast<float2*>(&Yb[(size_t)(o0 + 8) * T_ + t]) = v1;
        }
    }
}

template<int KW>
__global__ __launch_bounds__(256) void k_mma(
    const float* __restrict__ X, const float* __restrict__ Wg,
    const float* __restrict__ bias, float* __restrict__ Y,
    int M, int Cin, int relu)
{
    const int b = blockIdx.z;
    mma_body<KW>(X + (size_t)b * Cin * T_, Wg, bias, Y + (size_t)b * M * T_,
                 Cin, relu, blockIdx.y * 64, blockIdx.x * 64, 0, Cin);
}

__global__ __launch_bounds__(256) void k_qkv(
    const float* __restrict__ X,
    const float* __restrict__ Wq, const float* __restrict__ bq, float* __restrict__ Yq,
    const float* __restrict__ Wk, const float* __restrict__ bk, float* __restrict__ Yk,
    const float* __restrict__ Wv, const float* __restrict__ bv, float* __restrict__ Yv)
{
    const int b = blockIdx.z;
    const int mat = blockIdx.y / 3;
    const int m0  = (blockIdx.y % 3) * 64;
    const float *W, *bi; float *Y;
    if (mat == 0)      { W = Wq; bi = bq; Y = Yq; }
    else if (mat == 1) { W = Wk; bi = bk; Y = Yk; }
    else               { W = Wv; bi = bv; Y = Yv; }
    mma_body<1>(X + (size_t)b * C_ * T_, W, bi, Y + (size_t)b * C_ * T_,
                C_, 0, m0, blockIdx.x * 64, 0, C_);
}

__global__ __launch_bounds__(256) void k_conv2split(
    const float* __restrict__ X, const float* __restrict__ Wg,
    const float* __restrict__ bias, float* __restrict__ Y1, float* __restrict__ Y2)
{
    const int b = blockIdx.z;
    const int half = blockIdx.y / 3;
    const int m0   = (blockIdx.y % 3) * 64;
    float* Y = half ? Y2 : Y1;
    mma_body<3>(X + (size_t)b * FC_ * T_, Wg, half ? nullptr : bias,
                Y + (size_t)b * C_ * T_, FC_, 0, m0, blockIdx.x * 64,
                half * (FC_/2), (half + 1) * (FC_/2));
}

// ---------------- flash attention with fused rel-K band + rel-V correction ----
// Vs stored [d][s] (same as Ks); K/V loads float4-vectorized, conflict-free.
__global__ __launch_bounds__(128) void k_flash(
    const float* __restrict__ Q, const float* __restrict__ Kp, const float* __restrict__ V,
    const float* __restrict__ erk, const float* __restrict__ erv,
    float* __restrict__ O)
{
    constexpr int BR = 64, BC = 64, D = 96;
    constexpr int QSTR = 100, KSTR = 68, VSTR = 68, PSTR = 68;
    extern __shared__ float sm[];
    float* Qs = sm;                  // BR*QSTR  [r][d] tf32(q*scale)
    float* Ks = Qs + BR*QSTR;        // D*KSTR   [d][s] tf32
    float* Vs = Ks + D*KSTR;         // D*VSTR   [d][s] tf32
    float* Ps = Vs + D*VSTR;         // BR*PSTR  [r][s] tf32 probabilities
    float* qr = Ps + BR*PSTR;        // BR*9     q . erk
    float* bs = qr + BR*9;           // BR*12    band scores (init -1e30)
    float* ev = bs + BR*12;          // 9*96     erv staged

    const int t0 = blockIdx.x * BR;
    const int h = blockIdx.y, b = blockIdx.z;
    const size_t base = ((size_t)b * C_ + h * KC_) * T_;
    const float* Qb = Q + base;
    const float* Kb = Kp + base;
    const float* Vb = V + base;

    const int tid  = threadIdx.x;
    const int lane = tid & 31, w = tid >> 5;
    const int g = lane >> 2, tig = lane & 3;
    const int w16 = w * 16;

    for (int idx = tid; idx < D*BR; idx += 128) {
        int d = idx / BR, r = idx - d * BR;
        Qs[r*QSTR + d] = to_tf32(Qb[(size_t)d * T_ + t0 + r] * SCALE_);
    }
    for (int idx = tid; idx < 9*96; idx += 128) ev[idx] = erv[idx];
    for (int idx = tid; idx < BR*12; idx += 128) bs[idx] = -1e30f;
    __syncthreads();
    for (int idx = tid; idx < BR * 9; idx += 128) {
        int r = idx / 9, dd = idx - r * 9;
        float s = 0.f;
        #pragma unroll 8
        for (int d = 0; d < D; d++) s = fmaf(Qs[r*QSTR + d], erk[dd*KC_ + d], s);
        qr[idx] = s;
    }

    float m_i[2] = {-1e30f, -1e30f};
    float l_i[2] = {0.f, 0.f};
    float oa[12][4] = {};

    for (int s0 = 0; s0 < T_; s0 += BC) {
        __syncthreads();
        // vectorized K/V tile load: 96 rows x 16 float4 chunks each
        #pragma unroll
        for (int j = 0; j < 12; j++) {
            int idx = tid + j*128;           // 0 .. 1535
            int d  = idx >> 4;
            int s4 = (idx & 15) * 4;
            float4 kv = *reinterpret_cast<const float4*>(&Kb[(size_t)d * T_ + s0 + s4]);
            float4 vv = *reinterpret_cast<const float4*>(&Vb[(size_t)d * T_ + s0 + s4]);
            float4 ko = make_float4(to_tf32(kv.x), to_tf32(kv.y), to_tf32(kv.z), to_tf32(kv.w));
            float4 vo = make_float4(to_tf32(vv.x), to_tf32(vv.y), to_tf32(vv.z), to_tf32(vv.w));
            *reinterpret_cast<float4*>(&Ks[d*KSTR + s4]) = ko;
            *reinterpret_cast<float4*>(&Vs[d*VSTR + s4]) = vo;
        }
        __syncthreads();

        // ---- S = Q K^T ----
        float acc[8][4];
        #pragma unroll
        for (int nf = 0; nf < 8; nf++)
            #pragma unroll
            for (int e = 0; e < 4; e++) acc[nf][e] = 0.f;

        #pragma unroll
        for (int kk = 0; kk < D; kk += 8) {
            float a[4];
            a[0] = Qs[(w16 + g    )*QSTR + kk + tig    ];
            a[1] = Qs[(w16 + g + 8)*QSTR + kk + tig    ];
            a[2] = Qs[(w16 + g    )*QSTR + kk + tig + 4];
            a[3] = Qs[(w16 + g + 8)*QSTR + kk + tig + 4];
            #pragma unroll
            for (int nf = 0; nf < 8; nf++) {
                float bfr[2];
                bfr[0] = Ks[(kk + tig    )*KSTR + nf*8 + g];
                bfr[1] = Ks[(kk + tig + 4)*KSTR + nf*8 + g];
                mma_tf32(acc[nf], a, bfr);
            }
        }

        // ---- rel-K band add + band-score spill (diagonal tiles only) ----
        if (s0 + BC + 4 > t0 && s0 < t0 + BR + 5) {
            #pragma unroll
            for (int nf = 0; nf < 8; nf++)
                #pragma unroll
                for (int e = 0; e < 2; e++) {
                    int col = s0 + nf*8 + 2*tig + e;
                    int r0 = t0 + w16 + g;
                    int d0 = col - r0;
                    if (d0 >= -4 && d0 <= 4) {
                        acc[nf][e] += qr[(w16 + g)*9 + d0 + 4];
                        bs[(w16 + g)*12 + d0 + 4] = acc[nf][e];
                    }
                    int d1 = col - (r0 + 8);
                    if (d1 >= -4 && d1 <= 4) {
                        acc[nf][e + 2] += qr[(w16 + g + 8)*9 + d1 + 4];
                        bs[(w16 + g + 8)*12 + d1 + 4] = acc[nf][e + 2];
                    }
                }
        }

        // ---- online softmax (rows g and g+8; reduce over tig group) ----
        #pragma unroll
        for (int i = 0; i < 2; i++) {
            float mx = -1e30f;
            #pragma unroll
            for (int nf = 0; nf < 8; nf++)
                mx = fmaxf(mx, fmaxf(acc[nf][2*i], acc[nf][2*i + 1]));
            mx = fmaxf(mx, __shfl_xor_sync(0xffffffffu, mx, 1));
            mx = fmaxf(mx, __shfl_xor_sync(0xffffffffu, mx, 2));
            float mn = fmaxf(m_i[i], mx);
            float al = __expf(m_i[i] - mn);
            float rs = 0.f;
            int row = w16 + g + 8*i;
            #pragma unroll
            for (int nf = 0; nf < 8; nf++) {
                float p0 = to_tf32(__expf(acc[nf][2*i    ] - mn));
                float p1 = to_tf32(__expf(acc[nf][2*i + 1] - mn));
                *reinterpret_cast<float2*>(&Ps[row*PSTR + nf*8 + 2*tig]) = make_float2(p0, p1);
                rs += p0 + p1;
            }
            rs += __shfl_xor_sync(0xffffffffu, rs, 1);
            rs += __shfl_xor_sync(0xffffffffu, rs, 2);
            l_i[i] = l_i[i] * al + rs;
            m_i[i] = mn;
            #pragma unroll
            for (int nf = 0; nf < 12; nf++) {
                oa[nf][2*i] *= al; oa[nf][2*i + 1] *= al;
            }
        }
        __syncwarp();

        // ---- O += P @ V : B-fragment from Vs [d][s] (n=d, k=s) ----
        #pragma unroll
        for (int kk = 0; kk < BC; kk += 8) {
            float pa[4];
            pa[0] = Ps[(w16 + g    )*PSTR + kk + tig    ];
            pa[1] = Ps[(w16 + g + 8)*PSTR + kk + tig    ];
            pa[2] = Ps[(w16 + g    )*PSTR + kk + tig + 4];
            pa[3] = Ps[(w16 + g + 8)*PSTR + kk + tig + 4];
            #pragma unroll
            for (int nf = 0; nf < 12; nf++) {
                float bfr[2];
                bfr[0] = Vs[(nf*8 + g)*VSTR + kk + tig    ];
                bfr[1] = Vs[(nf*8 + g)*VSTR + kk + tig + 4];
                mma_tf32(oa[nf], pa, bfr);
            }
        }
    }
    __syncthreads();   // also orders bs writes before epilogue reads

    // ---- epilogue: band probs from final (m,l); normalize + add erv term ----
    {
        float inv0 = 1.f / l_i[0], inv1 = 1.f / l_i[1];
        float p0[9], p1[9];
        #pragma unroll
        for (int dd = 0; dd < 9; dd++) {
            p0[dd] = __expf(bs[(w16 + g    )*12 + dd] - m_i[0]) * inv0;
            p1[dd] = __expf(bs[(w16 + g + 8)*12 + dd] - m_i[1]) * inv1;
        }
        #pragma unroll
        for (int nf = 0; nf < 12; nf++) {
            #pragma unroll
            for (int e = 0; e < 2; e++) {
                int d = nf*8 + 2*tig + e;
                float add0 = 0.f, add1 = 0.f;
                #pragma unroll
                for (int dd = 0; dd < 9; dd++) {
                    float evd = ev[dd*96 + d];
                    add0 = fmaf(p0[dd], evd, add0);
                    add1 = fmaf(p1[dd], evd, add1);
                }
                Qs[d*BR + w16 + g    ] = oa[nf][e    ] * inv0 + add0;
                Qs[d*BR + w16 + g + 8] = oa[nf][e + 2] * inv1 + add1;
            }
        }
    }
    __syncthreads();
    float* Ob = O + base;
    for (int idx = tid; idx < D*BR; idx += 128) {
        int d = idx / BR, r = idx - d * BR;
        Ob[(size_t)d * T_ + t0 + r] = Qs[idx];
    }
}

// ---------------- fused residual-add + channel LayerNorm ----------------
__global__ __launch_bounds__(256) void k_addln(
    float* __restrict__ X, const float* __restrict__ R,
    const float* __restrict__ gg, const float* __restrict__ be)
{
    const int tx = threadIdx.x, ty = threadIdx.y;
    const int t = blockIdx.x * 32 + tx;
    const int b = blockIdx.y;

    float vals[24];
    float s = 0.f, sq = 0.f;
    #pragma unroll
    for (int k = 0; k < 24; k++) {
        int c = ty + k * 8;
        size_t idx = ((size_t)b * C_ + c) * T_ + t;
        float v = X[idx] + R[idx];
        vals[k] = v; s += v; sq += v * v;
    }
    __shared__ float ss[8][33], sg[8][33];
    ss[ty][tx] = s; sg[ty][tx] = sq;
    __syncthreads();
    if (ty == 0) {
        float a = 0.f, q = 0.f;
        #pragma unroll
        for (int k = 0; k < 8; k++) { a += ss[k][tx]; q += sg[k][tx]; }
        ss[0][tx] = a; sg[0][tx] = q;
    }
    __syncthreads();
    const float mean = ss[0][tx] * (1.f / C_);
    const float var  = sg[0][tx] * (1.f / C_) - mean * mean;
    const float rstd = rsqrtf(var + EPS_);
    #pragma unroll
    for (int k = 0; k < 24; k++) {
        int c = ty + k * 8;
        size_t idx = ((size_t)b * C_ + c) * T_ + t;
        X[idx] = (vals[k] - mean) * rstd * gg[c] + be[c];
    }
}

__global__ __launch_bounds__(256) void k_addln3(
    float* __restrict__ X, const float* __restrict__ R1, const float* __restrict__ R2,
    const float* __restrict__ gg, const float* __restrict__ be)
{
    const int tx = threadIdx.x, ty = threadIdx.y;
    const int t = blockIdx.x * 32 + tx;
    const int b = blockIdx.y;

    float vals[24];
    float s = 0.f, sq = 0.f;
    #pragma unroll
    for (int k = 0; k < 24; k++) {
        int c = ty + k * 8;
        size_t idx = ((size_t)b * C_ + c) * T_ + t;
        float v = X[idx] + R1[idx] + R2[idx];
        vals[k] = v; s += v; sq += v * v;
    }
    __shared__ float ss[8][33], sg[8][33];
    ss[ty][tx] = s; sg[ty][tx] = sq;
    __syncthreads();
    if (ty == 0) {
        float a = 0.f, q = 0.f;
        #pragma unroll
        for (int k = 0; k < 8; k++) { a += ss[k][tx]; q += sg[k][tx]; }
        ss[0][tx] = a; sg[0][tx] = q;
    }
    __syncthreads();
    const float mean = ss[0][tx] * (1.f / C_);
    const float var  = sg[0][tx] * (1.f / C_) - mean * mean;
    const float rstd = rsqrtf(var + EPS_);
    #pragma unroll
    for (int k = 0; k < 24; k++) {
        int c = ty + k * 8;
        size_t idx = ((size_t)b * C_ + c) * T_ + t;
        X[idx] = (vals[k] - mean) * rstd * gg[c] + be[c];
    }
}

// ---------------- launcher ----------------
extern "C" void kernel_launch(void* const* d_in, const int* in_sizes, int n_in,
                              void* d_out, int out_size)
{
    (void)in_sizes; (void)n_in; (void)out_size;
    const float* x   = (const float*)d_in[0];
    const float* msk = (const float*)d_in[1];
    const float* Wq  = (const float*)d_in[2];
    const float* bq  = (const float*)d_in[3];
    const float* Wk  = (const float*)d_in[4];
    const float* bk  = (const float*)d_in[5];
    const float* Wv  = (const float*)d_in[6];
    const float* bv  = (const float*)d_in[7];
    const float* Wo  = (const float*)d_in[8];
    const float* bo  = (const float*)d_in[9];
    const float* erk = (const float*)d_in[10];
    const float* erv = (const float*)d_in[11];
    const float* g1  = (const float*)d_in[12];
    const float* be1 = (const float*)d_in[13];
    const float* fw1 = (const float*)d_in[14];
    const float* fb1 = (const float*)d_in[15];
    const float* fw2 = (const float*)d_in[16];
    const float* fb2 = (const float*)d_in[17];
    const float* g2  = (const float*)d_in[18];
    const float* be2 = (const float*)d_in[19];

    float *xb, *qb, *kb, *vb, *ab, *tb, *fb;
    cudaGetSymbolAddress((void**)&xb, g_x);
    cudaGetSymbolAddress((void**)&qb, g_q);
    cudaGetSymbolAddress((void**)&kb, g_k);
    cudaGetSymbolAddress((void**)&vb, g_v);
    cudaGetSymbolAddress((void**)&ab, g_a);
    cudaGetSymbolAddress((void**)&tb, g_t);
    cudaGetSymbolAddress((void**)&fb, g_f);

    constexpr int FLASH_SMEM =
        (64*100 + 96*68 + 96*68 + 64*68 + 64*9 + 64*12 + 9*96) * 4;
    cudaFuncSetAttribute(k_flash, cudaFuncAttributeMaxDynamicSharedMemorySize, FLASH_SMEM);

    k_maskmul<<<(B_*C_*T_ + 255)/256, 256>>>(x, msk, xb);

    for (int i = 0; i < L_; i++) {
        k_qkv<<<dim3(T_/64, 9, B_), 256>>>(
            xb,
            Wq + (size_t)i*C_*C_, bq + i*C_, qb,
            Wk + (size_t)i*C_*C_, bk + i*C_, kb,
            Wv + (size_t)i*C_*C_, bv + i*C_, vb);

        k_flash<<<dim3(T_/64, H_, B_), 128, FLASH_SMEM>>>(
            qb, kb, vb, erk + (size_t)i*9*KC_, erv + (size_t)i*9*KC_, ab);

        k_mma<1><<<dim3(T_/64, C_/64, B_), 256>>>(
            ab, Wo + (size_t)i*C_*C_, bo + i*C_, tb, C_, C_, 0);
        k_addln<<<dim3(T_/32, B_), dim3(32, 8)>>>(xb, tb, g1 + i*C_, be1 + i*C_);

        k_mma<3><<<dim3(T_/64, FC_/64, B_), 256>>>(
            xb, fw1 + (size_t)i*FC_*C_*3, fb1 + i*FC_, fb, FC_, C_, 1);

        k_conv2split<<<dim3(T_/64, 6, B_), 256>>>(
            fb, fw2 + (size_t)i*C_*FC_*3, fb2 + i*C_, tb, ab);
        k_addln3<<<dim3(T_/32, B_), dim3(32, 8)>>>(xb, tb, ab, g2 + i*C_, be2 + i*C_);
    }

    k_maskmul<<<(B_*C_*T_ + 255)/256, 256>>>(xb, msk, (float*)d_out);
}